// round 2
// baseline (speedup 1.0000x reference)
#include <cuda_runtime.h>
#include <cstdint>

// Embedding gather: out[i, :] = table[idx[i], :]
//   table: [1,000,000 x 128] float32  (512 MB)
//   idx:   [1,048,576] int64 OR int32 (JAX may silently downcast int64->int32)
//   out:   [1,048,576 x 128] float32  (512 MiB)
//
// One warp handles ROWS_PER_WARP rows; each lane moves one float4 (16 B),
// so a row (128 floats = 512 B) = 32 lanes x float4 = 4 full 128B sectors,
// fully coalesced on both the gather read and the stream write.

#define ROWS_PER_WARP 2

// 1 = indices are int64, 0 = indices are int32. Set by probe kernel.
__device__ int g_idx_is_i64;

// Probe: for int64 indices in [0, 1e6), every odd (high) 32-bit word is 0.
// For int32 indices, odd words are themselves random indices (mostly nonzero).
// Checking 128 odd words makes misclassification probability ~0.
__global__ void probe_idx_dtype_kernel(const unsigned int* __restrict__ idx_words,
                                       long long n_words)
{
    // single warp
    int lane = threadIdx.x;
    int all_hi_zero = 1;
#pragma unroll
    for (int j = 0; j < 4; j++) {
        long long w = 2 * (lane + 32 * j) + 1;  // odd words 1,3,...,255
        if (w < n_words && idx_words[w] != 0u) all_hi_zero = 0;
    }
    unsigned int ballot = __ballot_sync(0xFFFFFFFFu, all_hi_zero);
    if (lane == 0) g_idx_is_i64 = (ballot == 0xFFFFFFFFu) ? 1 : 0;
}

__global__ void __launch_bounds__(256) embedding_gather_kernel(
    const void* __restrict__ idx_raw,
    const float4* __restrict__ table,   // table viewed as [N_EMB x 32] float4
    float4* __restrict__ out,           // out   viewed as [N_IDX x 32] float4
    int n_rows)
{
    const int lane = threadIdx.x & 31;
    const int warp_global = (int)((blockIdx.x * blockDim.x + threadIdx.x) >> 5);

    int row0 = warp_global * ROWS_PER_WARP;
    if (row0 >= n_rows) return;

    const bool is64 = (g_idx_is_i64 != 0);   // uniform across grid
    const long long* idx64 = (const long long*)idx_raw;
    const int*       idx32 = (const int*)idx_raw;

    // Batch independent index loads and row loads to raise per-warp MLP.
    long long r[ROWS_PER_WARP];
#pragma unroll
    for (int j = 0; j < ROWS_PER_WARP; j++) {
        int row = row0 + j;
        if (row < n_rows) {
            r[j] = is64 ? idx64[row] : (long long)idx32[row];
        } else {
            r[j] = 0;
        }
    }

    float4 v[ROWS_PER_WARP];
#pragma unroll
    for (int j = 0; j < ROWS_PER_WARP; j++) {
        v[j] = __ldg(&table[(size_t)r[j] * 32 + lane]);
    }

#pragma unroll
    for (int j = 0; j < ROWS_PER_WARP; j++) {
        int row = row0 + j;
        if (row < n_rows) {
            out[(size_t)row * 32 + lane] = v[j];
        }
    }
}

extern "C" void kernel_launch(void* const* d_in, const int* in_sizes, int n_in,
                              void* d_out, int out_size)
{
    // Identify inputs by element count, not order:
    //   idx   has   1,048,576 elements
    //   table has 128,000,000 elements (float32)
    const void* p0 = d_in[0];
    const void* p1 = d_in[1];
    long long s0 = in_sizes[0];
    long long s1 = in_sizes[1];

    const void* idx;
    const float* table;
    long long n_rows;
    if (s0 < s1) {
        idx = p0;
        table = (const float*)p1;
        n_rows = s0;
    } else {
        idx = p1;
        table = (const float*)p0;
        n_rows = s1;
    }

    float* out = (float*)d_out;

    // Probe index dtype (int32 vs int64). If indices are int64, the buffer has
    // 2*n_rows 32-bit words; if int32, n_rows words. Bound the probe by the
    // smaller (int32) interpretation so it never reads past the buffer.
    probe_idx_dtype_kernel<<<1, 32>>>((const unsigned int*)idx, n_rows);

    const int threads = 256;                      // 8 warps/block
    const long long warps_needed = (n_rows + ROWS_PER_WARP - 1) / ROWS_PER_WARP;
    const int blocks = (int)((warps_needed * 32 + threads - 1) / threads);

    embedding_gather_kernel<<<blocks, threads>>>(
        idx, (const float4*)table, (float4*)out, (int)n_rows);
}

// round 3
// speedup vs baseline: 1.1182x; 1.1182x over previous
#include <cuda_runtime.h>
#include <cstdint>

// Embedding gather: out[i, :] = table[idx[i], :]
//   table: [1,000,000 x 128] float32  (512 MB)
//   idx:   [1,048,576] int64 OR int32 (JAX may silently downcast int64->int32)
//   out:   [1,048,576 x 128] float32  (512 MiB)
//
// One warp handles ROWS_PER_WARP rows; each lane moves one float4 (16 B),
// so a row (128 floats = 512 B) = 32 lanes x float4 = 4 full 128B sectors,
// fully coalesced on both the gather read and the stream write.
//
// R3 changes vs R2 baseline (175.8us kernel, DRAM 69%):
//  - ROWS_PER_WARP 2 -> 4: doubles per-thread MLP to hide DRAM latency.
//  - __stcs on output stores + __ldcs on index loads: evict-first so the
//    512MiB write stream does not evict table lines from L2; repeat-index
//    gathers (~400K of 1.05M) then hit L2 instead of DRAM.

#define ROWS_PER_WARP 4

// 1 = indices are int64, 0 = indices are int32. Set by probe kernel.
__device__ int g_idx_is_i64;

// Probe: for int64 indices in [0, 1e6), every odd (high) 32-bit word is 0.
// For int32 indices, odd words are themselves random indices (mostly nonzero).
__global__ void probe_idx_dtype_kernel(const unsigned int* __restrict__ idx_words,
                                       long long n_words)
{
    int lane = threadIdx.x;
    int all_hi_zero = 1;
#pragma unroll
    for (int j = 0; j < 4; j++) {
        long long w = 2 * (lane + 32 * j) + 1;  // odd words 1,3,...,255
        if (w < n_words && idx_words[w] != 0u) all_hi_zero = 0;
    }
    unsigned int ballot = __ballot_sync(0xFFFFFFFFu, all_hi_zero);
    if (lane == 0) g_idx_is_i64 = (ballot == 0xFFFFFFFFu) ? 1 : 0;
}

__global__ void __launch_bounds__(256) embedding_gather_kernel(
    const void* __restrict__ idx_raw,
    const float4* __restrict__ table,   // table viewed as [N_EMB x 32] float4
    float4* __restrict__ out,           // out   viewed as [N_IDX x 32] float4
    int n_rows)
{
    const int lane = threadIdx.x & 31;
    const int warp_global = (int)((blockIdx.x * blockDim.x + threadIdx.x) >> 5);

    int row0 = warp_global * ROWS_PER_WARP;
    if (row0 >= n_rows) return;

    const bool is64 = (g_idx_is_i64 != 0);   // uniform across grid
    const long long* idx64 = (const long long*)idx_raw;
    const int*       idx32 = (const int*)idx_raw;

    // Batch independent index loads and row loads to raise per-warp MLP.
    long long r[ROWS_PER_WARP];
#pragma unroll
    for (int j = 0; j < ROWS_PER_WARP; j++) {
        int row = row0 + j;
        if (row < n_rows) {
            r[j] = is64 ? (long long)__ldcs(&idx64[row])
                        : (long long)__ldcs(&idx32[row]);
        } else {
            r[j] = 0;
        }
    }

    float4 v[ROWS_PER_WARP];
#pragma unroll
    for (int j = 0; j < ROWS_PER_WARP; j++) {
        v[j] = __ldg(&table[(size_t)r[j] * 32 + lane]);   // cache in L2 (reuse on dup idx)
    }

#pragma unroll
    for (int j = 0; j < ROWS_PER_WARP; j++) {
        int row = row0 + j;
        if (row < n_rows) {
            __stcs(&out[(size_t)row * 32 + lane], v[j]);  // evict-first: don't pollute L2
        }
    }
}

extern "C" void kernel_launch(void* const* d_in, const int* in_sizes, int n_in,
                              void* d_out, int out_size)
{
    // Identify inputs by element count, not order:
    //   idx   has   1,048,576 elements
    //   table has 128,000,000 elements (float32)
    const void* p0 = d_in[0];
    const void* p1 = d_in[1];
    long long s0 = in_sizes[0];
    long long s1 = in_sizes[1];

    const void* idx;
    const float* table;
    long long n_rows;
    if (s0 < s1) {
        idx = p0;
        table = (const float*)p1;
        n_rows = s0;
    } else {
        idx = p1;
        table = (const float*)p0;
        n_rows = s1;
    }

    float* out = (float*)d_out;

    probe_idx_dtype_kernel<<<1, 32>>>((const unsigned int*)idx, n_rows);

    const int threads = 256;                      // 8 warps/block
    const long long warps_needed = (n_rows + ROWS_PER_WARP - 1) / ROWS_PER_WARP;
    const int blocks = (int)((warps_needed * 32 + threads - 1) / threads);

    embedding_gather_kernel<<<blocks, threads>>>(
        idx, (const float4*)table, (float4*)out, (int)n_rows);
}